// round 2
// baseline (speedup 1.0000x reference)
#include <cuda_runtime.h>
#include <cstdint>

#define N_NODES 50000
#define E_EDGES 800000
#define DIM 128
#define NEG_INIT -1e9f

// Scratch (static device globals — no runtime allocation allowed)
__device__ float g_agg[(size_t)N_NODES * DIM];
__device__ float g_h[(size_t)N_NODES * DIM];
__device__ int   g_is64;   // 1 if edge_index buffer is int64, 0 if int32

// ---------------------------------------------------------------------------
// Kernel D: detect edge_index dtype. Single block. Looks at 256 odd int32
// words at spread positions 2k+1 (k < E). Under an int64 layout these are the
// high words of non-negative values < 2^31 -> all zero. Under int32 they are
// random node ids; all-zero has ~0 probability. Deterministic per input.
// ---------------------------------------------------------------------------
__global__ void detect_dtype_kernel(const int* __restrict__ ei32) {
    __shared__ int any_nonzero;
    if (threadIdx.x == 0) any_nonzero = 0;
    __syncthreads();
    int k = (int)threadIdx.x * 3000;          // 0 .. 765000 < E_EDGES
    if (ei32[2 * k + 1] != 0) atomicOr(&any_nonzero, 1);
    __syncthreads();
    if (threadIdx.x == 0) g_is64 = any_nonzero ? 0 : 1;
}

// ---------------------------------------------------------------------------
// Kernel 0: init agg to -1e9
// ---------------------------------------------------------------------------
__global__ void init_agg_kernel() {
    int i = blockIdx.x * blockDim.x + threadIdx.x;
    const int n4 = (N_NODES * DIM) / 4;
    if (i < n4) {
        ((float4*)g_agg)[i] = make_float4(NEG_INIT, NEG_INIT, NEG_INIT, NEG_INIT);
    }
}

// ---------------------------------------------------------------------------
// Kernel 1: scatter-max of messages = x[src] * ew into g_agg[dst]
// One warp per edge; lane handles 4 contiguous floats (float4).
// Float atomic-max via int-max (v>=0) / uint-min (v<0) bit trick; valid
// because init is negative (-1e9) and orderings compose across sign domains.
// ---------------------------------------------------------------------------
__device__ __forceinline__ void atom_max_float(float* addr, float v) {
    if (v >= 0.0f) {
        atomicMax((int*)addr, __float_as_int(v));
    } else {
        atomicMin((unsigned int*)addr, __float_as_uint(v));
    }
}

__global__ void scatter_max_kernel(const float* __restrict__ x,
                                   const void* __restrict__ ei,
                                   const float* __restrict__ ew) {
    int e = blockIdx.x * (blockDim.x >> 5) + (threadIdx.x >> 5);
    if (e >= E_EDGES) return;
    int lane = threadIdx.x & 31;

    int src, dst;
    if (g_is64) {
        const long long* e64 = (const long long*)ei;
        src = (int)e64[e];
        dst = (int)e64[(size_t)E_EDGES + e];
    } else {
        const int* e32 = (const int*)ei;
        src = e32[e];
        dst = e32[(size_t)E_EDGES + e];
    }
    // Defensive: never form an out-of-bounds address.
    if ((unsigned)src >= N_NODES || (unsigned)dst >= N_NODES) return;

    float w = ew[e];

    float4 v = ((const float4*)(x + (size_t)src * DIM))[lane];
    v.x *= w; v.y *= w; v.z *= w; v.w *= w;

    float* a = g_agg + (size_t)dst * DIM + lane * 4;
    atom_max_float(a + 0, v.x);
    atom_max_float(a + 1, v.y);
    atom_max_float(a + 2, v.z);
    atom_max_float(a + 3, v.w);
}

// ---------------------------------------------------------------------------
// Kernel 2/3: fused GEMM  OUT[m, o] = act( IN[m, :] @ W[o, :]^T + B[o] )
// Templated: FUSE_INPUT builds IN = (1+eps)*x + (agg == -1e9 ? 0 : agg) on the
// fly while staging; LEAKY applies LeakyReLU(0.01) in the epilogue.
//
// BM=64 rows x BN=128 cols per CTA, 256 threads, 4x8 register tile per thread.
// W staged transposed into SMEM with LDW=132 padding. 101,376 B dyn smem
// -> 2 CTA/SM.
// ---------------------------------------------------------------------------
#define LDW 132
#define BM 64
#define SMEM_BYTES ((128 * LDW + BM * LDW) * 4)

template <bool FUSE_INPUT, bool LEAKY>
__global__ void __launch_bounds__(256, 2)
mlp_gemm_kernel(const float* __restrict__ A,
                const float* __restrict__ AGG,
                const float* __restrict__ W,
                const float* __restrict__ B,
                const float* __restrict__ EPS,
                float* __restrict__ OUT) {
    extern __shared__ float sm[];
    float* wT = sm;                 // [128][LDW]
    float* xs = sm + 128 * LDW;     // [BM][LDW]

    const int tid = threadIdx.x;    // 256 threads
    const int m0 = blockIdx.x * BM;

    // Stage W transposed: wT[k][o] = W[o*128 + k]
    for (int idx = tid; idx < 128 * 128; idx += 256) {
        int o = idx >> 7;
        int k = idx & 127;
        wT[k * LDW + o] = W[idx];
    }

    // Stage input tile: xs[r][c] (optionally fused with agg/eps)
    float scale = 1.0f;
    if (FUSE_INPUT) scale = 1.0f + EPS[0];
    #pragma unroll
    for (int p = 0; p < 8; ++p) {
        int r = p * 8 + (tid >> 5);   // 0..63
        int c4 = tid & 31;            // float4 column 0..31
        int m = m0 + r;
        float4 v = make_float4(0.f, 0.f, 0.f, 0.f);
        if (m < N_NODES) {
            v = ((const float4*)(A + (size_t)m * DIM))[c4];
            if (FUSE_INPUT) {
                float4 g = ((const float4*)(AGG + (size_t)m * DIM))[c4];
                v.x = scale * v.x + (g.x == NEG_INIT ? 0.0f : g.x);
                v.y = scale * v.y + (g.y == NEG_INIT ? 0.0f : g.y);
                v.z = scale * v.z + (g.z == NEG_INIT ? 0.0f : g.z);
                v.w = scale * v.w + (g.w == NEG_INIT ? 0.0f : g.w);
            }
        }
        float* row = xs + r * LDW + c4 * 4;
        row[0] = v.x; row[1] = v.y; row[2] = v.z; row[3] = v.w;
    }
    __syncthreads();

    const int tm = tid >> 4;   // 0..15 -> rows tm*4 .. tm*4+3
    const int tn = tid & 15;   // 0..15 -> cols tn*8 .. tn*8+7

    float acc[4][8];
    #pragma unroll
    for (int i = 0; i < 4; ++i)
        #pragma unroll
        for (int j = 0; j < 8; ++j) acc[i][j] = 0.0f;

    #pragma unroll 4
    for (int k = 0; k < 128; ++k) {
        float a[4];
        #pragma unroll
        for (int i = 0; i < 4; ++i) a[i] = xs[(tm * 4 + i) * LDW + k];
        float4 b0 = *(const float4*)(wT + k * LDW + tn * 8);
        float4 b1 = *(const float4*)(wT + k * LDW + tn * 8 + 4);
        float b[8] = {b0.x, b0.y, b0.z, b0.w, b1.x, b1.y, b1.z, b1.w};
        #pragma unroll
        for (int i = 0; i < 4; ++i)
            #pragma unroll
            for (int j = 0; j < 8; ++j)
                acc[i][j] = fmaf(a[i], b[j], acc[i][j]);
    }

    // Epilogue: bias (+activation) and store
    float bias[8];
    #pragma unroll
    for (int j = 0; j < 8; ++j) bias[j] = B[tn * 8 + j];

    #pragma unroll
    for (int i = 0; i < 4; ++i) {
        int m = m0 + tm * 4 + i;
        if (m < N_NODES) {
            float o[8];
            #pragma unroll
            for (int j = 0; j < 8; ++j) {
                float v = acc[i][j] + bias[j];
                if (LEAKY) v = (v >= 0.0f) ? v : 0.01f * v;
                o[j] = v;
            }
            float4* dst = (float4*)(OUT + (size_t)m * DIM + tn * 8);
            dst[0] = make_float4(o[0], o[1], o[2], o[3]);
            dst[1] = make_float4(o[4], o[5], o[6], o[7]);
        }
    }
}

// ---------------------------------------------------------------------------
// Launcher
// ---------------------------------------------------------------------------
extern "C" void kernel_launch(void* const* d_in, const int* in_sizes, int n_in,
                              void* d_out, int out_size) {
    const float* x   = (const float*)d_in[0];
    const void*  ei  = d_in[1];                 // int32 or int64 — detected on device
    const float* ew  = (const float*)d_in[2];
    const float* w1  = (const float*)d_in[3];
    const float* b1  = (const float*)d_in[4];
    const float* w2  = (const float*)d_in[5];
    const float* b2  = (const float*)d_in[6];
    const float* eps = (const float*)d_in[7];
    float*       out = (float*)d_out;

    // Host-side, non-stream ops: graph-capture safe, idempotent.
    cudaFuncSetAttribute(mlp_gemm_kernel<true, true>,
                         cudaFuncAttributeMaxDynamicSharedMemorySize, SMEM_BYTES);
    cudaFuncSetAttribute(mlp_gemm_kernel<false, false>,
                         cudaFuncAttributeMaxDynamicSharedMemorySize, SMEM_BYTES);

    void* agg_p = nullptr;
    void* h_p = nullptr;
    cudaGetSymbolAddress(&agg_p, g_agg);
    cudaGetSymbolAddress(&h_p, g_h);
    float* agg = (float*)agg_p;
    float* h   = (float*)h_p;

    // D) detect index dtype (writes g_is64)
    detect_dtype_kernel<<<1, 256>>>((const int*)ei);

    // 0) init agg = -1e9
    {
        int n4 = (N_NODES * DIM) / 4;
        init_agg_kernel<<<(n4 + 255) / 256, 256>>>();
    }

    // 1) scatter-max (warp per edge)
    {
        int warps_per_block = 8;
        int blocks = (E_EDGES + warps_per_block - 1) / warps_per_block;
        scatter_max_kernel<<<blocks, warps_per_block * 32>>>(x, ei, ew);
    }

    // 2) GEMM1 fused with (1+eps)*x + agg, + b1, LeakyReLU -> g_h
    {
        int blocks = (N_NODES + BM - 1) / BM;
        mlp_gemm_kernel<true, true><<<blocks, 256, SMEM_BYTES>>>(
            x, agg, w1, b1, eps, h);
    }

    // 3) GEMM2: g_h @ w2^T + b2 -> out
    {
        int blocks = (N_NODES + BM - 1) / BM;
        mlp_gemm_kernel<false, false><<<blocks, 256, SMEM_BYTES>>>(
            h, nullptr, w2, b2, eps, out);
    }
}

// round 3
// speedup vs baseline: 1.1528x; 1.1528x over previous
#include <cuda_runtime.h>
#include <cstdint>

#define N_NODES 50000
#define E_EDGES 800000
#define DIM 128
#define NEG_INF_F __int_as_float(0xff800000)

// ---------------------------------------------------------------------------
// Static device scratch (no runtime allocation allowed)
// ---------------------------------------------------------------------------
__device__ float g_agg[(size_t)N_NODES * DIM];
__device__ float g_h[(size_t)N_NODES * DIM];
__device__ int   g_is64;                  // 1 if edge_index is int64, else int32
__device__ int   g_cnt[N_NODES];          // per-dst edge counts
__device__ int   g_row[N_NODES + 1];      // CSR row offsets
__device__ int   g_cur[N_NODES];          // fill cursors
__device__ int2  g_edge[E_EDGES];         // {src, bits(weight)} bucketed by dst

// ---------------------------------------------------------------------------
// Dtype detect: odd int32 words at spread positions are all-zero iff int64.
// ---------------------------------------------------------------------------
__global__ void detect_dtype_kernel(const int* __restrict__ ei32) {
    __shared__ int any_nonzero;
    if (threadIdx.x == 0) any_nonzero = 0;
    __syncthreads();
    int k = (int)threadIdx.x * 3000;          // 0 .. 765000 < E_EDGES
    if (ei32[2 * k + 1] != 0) atomicOr(&any_nonzero, 1);
    __syncthreads();
    if (threadIdx.x == 0) g_is64 = any_nonzero ? 0 : 1;
}

__device__ __forceinline__ void load_edge(const void* ei, int e, int& src, int& dst) {
    if (g_is64) {
        const long long* e64 = (const long long*)ei;
        src = (int)e64[e];
        dst = (int)e64[(size_t)E_EDGES + e];
    } else {
        const int* e32 = (const int*)ei;
        src = e32[e];
        dst = e32[(size_t)E_EDGES + e];
    }
}

// ---------------------------------------------------------------------------
// CSR build: histogram -> scan -> fill
// ---------------------------------------------------------------------------
__global__ void hist_kernel(const void* __restrict__ ei) {
    int e = blockIdx.x * blockDim.x + threadIdx.x;
    if (e >= E_EDGES) return;
    int src, dst;
    load_edge(ei, e, src, dst);
    if ((unsigned)src < N_NODES && (unsigned)dst < N_NODES)
        atomicAdd(&g_cnt[dst], 1);
}

#define SCAN_T 1024
#define CHUNK  49            // 1024*49 = 50176 >= 50001
__global__ void scan_kernel() {
    __shared__ int sh[SCAN_T];
    int t = threadIdx.x;
    int base = t * CHUNK;
    int sum = 0;
    #pragma unroll
    for (int i = 0; i < CHUNK; ++i) {
        int idx = base + i;
        if (idx < N_NODES) sum += g_cnt[idx];
    }
    sh[t] = sum;
    __syncthreads();
    // Hillis-Steele inclusive scan
    for (int off = 1; off < SCAN_T; off <<= 1) {
        int v = (t >= off) ? sh[t - off] : 0;
        __syncthreads();
        sh[t] += v;
        __syncthreads();
    }
    int running = sh[t] - sum;   // exclusive base for this chunk
    #pragma unroll
    for (int i = 0; i < CHUNK; ++i) {
        int idx = base + i;
        if (idx <= N_NODES) g_row[idx] = running;
        if (idx < N_NODES) running += g_cnt[idx];
    }
}

__global__ void fill_kernel(const void* __restrict__ ei,
                            const float* __restrict__ ew) {
    int e = blockIdx.x * blockDim.x + threadIdx.x;
    if (e >= E_EDGES) return;
    int src, dst;
    load_edge(ei, e, src, dst);
    if ((unsigned)src >= N_NODES || (unsigned)dst >= N_NODES) return;
    int pos = g_row[dst] + atomicAdd(&g_cur[dst], 1);
    g_edge[pos] = make_int2(src, __float_as_int(ew[e]));
}

// ---------------------------------------------------------------------------
// Aggregate: one warp per dst node; lanes cover the 128-dim row (float4 each).
// Max in registers -> single clean write. Isolated nodes -> 0.
// ---------------------------------------------------------------------------
__global__ void agg_kernel(const float* __restrict__ x) {
    int warp = (blockIdx.x * blockDim.x + threadIdx.x) >> 5;
    if (warp >= N_NODES) return;
    int lane = threadIdx.x & 31;
    int beg = g_row[warp];
    int end = g_row[warp + 1];

    float4 acc = make_float4(NEG_INF_F, NEG_INF_F, NEG_INF_F, NEG_INF_F);
    for (int j = beg; j < end; ++j) {
        int2 ep = g_edge[j];
        float w = __int_as_float(ep.y);
        float4 v = ((const float4*)(x + (size_t)ep.x * DIM))[lane];
        acc.x = fmaxf(acc.x, v.x * w);
        acc.y = fmaxf(acc.y, v.y * w);
        acc.z = fmaxf(acc.z, v.z * w);
        acc.w = fmaxf(acc.w, v.w * w);
    }
    if (beg == end) acc = make_float4(0.f, 0.f, 0.f, 0.f);
    ((float4*)(g_agg + (size_t)warp * DIM))[lane] = acc;
}

// ---------------------------------------------------------------------------
// Packed fp32x2 helpers (sm_103a FFMA2 — PTX-only)
// ---------------------------------------------------------------------------
__device__ __forceinline__ unsigned long long pack2(float v) {
    unsigned long long r;
    asm("mov.b64 %0, {%1, %1};" : "=l"(r) : "f"(v));
    return r;
}
__device__ __forceinline__ void fma2(unsigned long long& d,
                                     unsigned long long a,
                                     unsigned long long b) {
    asm("fma.rn.f32x2 %0, %1, %2, %0;" : "+l"(d) : "l"(a), "l"(b));
}
__device__ __forceinline__ void unpack2(unsigned long long v, float& lo, float& hi) {
    asm("mov.b64 {%0, %1}, %2;" : "=f"(lo), "=f"(hi) : "l"(v));
}

// ---------------------------------------------------------------------------
// GEMM: OUT[m,o] = act( IN[m,:] @ W[o,:]^T + B[o] )
// FUSE_INPUT: IN = (1+eps)*x + agg  (agg already finalized; no sentinel check)
// BM=64 x BN=128, 256 threads, thread tile 4x8 (4 rows x 4 f32x2 col-pairs).
// W transposed in smem (LDW=132). x tile stored transposed (k-major, LDM=68)
// so the A operand is one LDS.128.
// ---------------------------------------------------------------------------
#define LDW 132
#define LDM 68
#define BM  64
#define SMEM_BYTES ((128 * LDW + 128 * LDM) * 4)   // 67584 + 34816 = 102400 B

template <bool FUSE_INPUT, bool LEAKY>
__global__ void __launch_bounds__(256, 2)
mlp_gemm_kernel(const float* __restrict__ A,
                const float* __restrict__ AGG,
                const float* __restrict__ W,
                const float* __restrict__ B,
                const float* __restrict__ EPS,
                float* __restrict__ OUT) {
    extern __shared__ float sm[];
    float* wT  = sm;                  // [k=128][o] stride LDW
    float* xsT = sm + 128 * LDW;      // [k=128][m] stride LDM

    const int tid = threadIdx.x;
    const int m0  = blockIdx.x * BM;

    // Stage W transposed: wT[k][o] = W[o*128 + k]
    for (int idx = tid; idx < 128 * 128; idx += 256) {
        int o = idx >> 7;
        int k = idx & 127;
        wT[k * LDW + o] = W[idx];
    }

    // Stage input tile transposed: xsT[c][r] (optionally fused with agg/eps)
    float scale = 1.0f;
    if (FUSE_INPUT) scale = 1.0f + EPS[0];
    #pragma unroll
    for (int p = 0; p < 8; ++p) {
        int r  = p * 8 + (tid >> 5);   // 0..63
        int c4 = tid & 31;             // float4 feature group
        int m  = m0 + r;
        float4 v = make_float4(0.f, 0.f, 0.f, 0.f);
        if (m < N_NODES) {
            v = ((const float4*)(A + (size_t)m * DIM))[c4];
            if (FUSE_INPUT) {
                float4 g = ((const float4*)(AGG + (size_t)m * DIM))[c4];
                v.x = scale * v.x + g.x;
                v.y = scale * v.y + g.y;
                v.z = scale * v.z + g.z;
                v.w = scale * v.w + g.w;
            }
        }
        xsT[(c4 * 4 + 0) * LDM + r] = v.x;
        xsT[(c4 * 4 + 1) * LDM + r] = v.y;
        xsT[(c4 * 4 + 2) * LDM + r] = v.z;
        xsT[(c4 * 4 + 3) * LDM + r] = v.w;
    }
    __syncthreads();

    const int tm = tid >> 4;   // 0..15 -> rows tm*4..tm*4+3
    const int tn = tid & 15;   // 0..15 -> cols tn*8..tn*8+7 (4 f32x2 pairs)

    unsigned long long acc[4][4];
    #pragma unroll
    for (int i = 0; i < 4; ++i)
        #pragma unroll
        for (int j = 0; j < 4; ++j) acc[i][j] = 0ull;

    const float* aBase = xsT + tm * 4;
    const float* bBase = wT + tn * 8;

    #pragma unroll 4
    for (int k = 0; k < 128; ++k) {
        float4 av = *(const float4*)(aBase + k * LDM);
        ulonglong2 bA = *(const ulonglong2*)(bBase + k * LDW);
        ulonglong2 bB = *(const ulonglong2*)(bBase + k * LDW + 4);
        unsigned long long a0 = pack2(av.x);
        unsigned long long a1 = pack2(av.y);
        unsigned long long a2 = pack2(av.z);
        unsigned long long a3 = pack2(av.w);
        fma2(acc[0][0], a0, bA.x); fma2(acc[0][1], a0, bA.y);
        fma2(acc[0][2], a0, bB.x); fma2(acc[0][3], a0, bB.y);
        fma2(acc[1][0], a1, bA.x); fma2(acc[1][1], a1, bA.y);
        fma2(acc[1][2], a1, bB.x); fma2(acc[1][3], a1, bB.y);
        fma2(acc[2][0], a2, bA.x); fma2(acc[2][1], a2, bA.y);
        fma2(acc[2][2], a2, bB.x); fma2(acc[2][3], a2, bB.y);
        fma2(acc[3][0], a3, bA.x); fma2(acc[3][1], a3, bA.y);
        fma2(acc[3][2], a3, bB.x); fma2(acc[3][3], a3, bB.y);
    }

    // Epilogue: bias (+LeakyReLU) and store
    float bias[8];
    #pragma unroll
    for (int j = 0; j < 8; ++j) bias[j] = B[tn * 8 + j];

    #pragma unroll
    for (int i = 0; i < 4; ++i) {
        int m = m0 + tm * 4 + i;
        if (m < N_NODES) {
            float o[8];
            #pragma unroll
            for (int j = 0; j < 4; ++j) unpack2(acc[i][j], o[2 * j], o[2 * j + 1]);
            #pragma unroll
            for (int j = 0; j < 8; ++j) {
                float v = o[j] + bias[j];
                if (LEAKY) v = (v >= 0.0f) ? v : 0.01f * v;
                o[j] = v;
            }
            float4* dst = (float4*)(OUT + (size_t)m * DIM + tn * 8);
            dst[0] = make_float4(o[0], o[1], o[2], o[3]);
            dst[1] = make_float4(o[4], o[5], o[6], o[7]);
        }
    }
}

// ---------------------------------------------------------------------------
// Launcher
// ---------------------------------------------------------------------------
extern "C" void kernel_launch(void* const* d_in, const int* in_sizes, int n_in,
                              void* d_out, int out_size) {
    const float* x   = (const float*)d_in[0];
    const void*  ei  = d_in[1];
    const float* ew  = (const float*)d_in[2];
    const float* w1  = (const float*)d_in[3];
    const float* b1  = (const float*)d_in[4];
    const float* w2  = (const float*)d_in[5];
    const float* b2  = (const float*)d_in[6];
    const float* eps = (const float*)d_in[7];
    float*       out = (float*)d_out;

    cudaFuncSetAttribute(mlp_gemm_kernel<true, true>,
                         cudaFuncAttributeMaxDynamicSharedMemorySize, SMEM_BYTES);
    cudaFuncSetAttribute(mlp_gemm_kernel<false, false>,
                         cudaFuncAttributeMaxDynamicSharedMemorySize, SMEM_BYTES);

    void *agg_p = nullptr, *h_p = nullptr, *cnt_p = nullptr, *cur_p = nullptr;
    cudaGetSymbolAddress(&agg_p, g_agg);
    cudaGetSymbolAddress(&h_p,   g_h);
    cudaGetSymbolAddress(&cnt_p, g_cnt);
    cudaGetSymbolAddress(&cur_p, g_cur);
    float* agg = (float*)agg_p;
    float* h   = (float*)h_p;

    // D) detect index dtype
    detect_dtype_kernel<<<1, 256>>>((const int*)ei);

    // CSR build
    cudaMemsetAsync(cnt_p, 0, N_NODES * sizeof(int));
    cudaMemsetAsync(cur_p, 0, N_NODES * sizeof(int));
    hist_kernel<<<(E_EDGES + 255) / 256, 256>>>(ei);
    scan_kernel<<<1, SCAN_T>>>();
    fill_kernel<<<(E_EDGES + 255) / 256, 256>>>(ei, ew);

    // Aggregate (warp per node)
    agg_kernel<<<(N_NODES * 32 + 255) / 256, 256>>>(x);

    // GEMM1 fused with (1+eps)*x + agg, + b1, LeakyReLU -> g_h
    {
        int blocks = (N_NODES + BM - 1) / BM;
        mlp_gemm_kernel<true, true><<<blocks, 256, SMEM_BYTES>>>(
            x, agg, w1, b1, eps, h);
    }
    // GEMM2: g_h @ w2^T + b2 -> out
    {
        int blocks = (N_NODES + BM - 1) / BM;
        mlp_gemm_kernel<false, false><<<blocks, 256, SMEM_BYTES>>>(
            h, nullptr, w2, b2, eps, out);
    }
}

// round 4
// speedup vs baseline: 1.6967x; 1.4719x over previous
#include <cuda_runtime.h>
#include <cstdint>

#define N_NODES 50000
#define E_EDGES 800000
#define DIM 128
#define NEG_INF_F __int_as_float(0xff800000)

// ---------------------------------------------------------------------------
// Static device scratch (no runtime allocation allowed)
// ---------------------------------------------------------------------------
__device__ float g_agg[(size_t)N_NODES * DIM];
__device__ float g_h[(size_t)N_NODES * DIM];
__device__ int   g_is64;                  // 1 if edge_index is int64, else int32
__device__ int   g_cnt[N_NODES];          // per-dst edge counts
__device__ int   g_row[N_NODES + 1];      // CSR row offsets
__device__ int   g_cur[N_NODES];          // fill cursors
__device__ int2  g_edge[E_EDGES];         // {src, bits(weight)} bucketed by dst

// ---------------------------------------------------------------------------
// Dtype detect: odd int32 words at spread positions are all-zero iff int64.
// ---------------------------------------------------------------------------
__global__ void detect_dtype_kernel(const int* __restrict__ ei32) {
    __shared__ int any_nonzero;
    if (threadIdx.x == 0) any_nonzero = 0;
    __syncthreads();
    int k = (int)threadIdx.x * 3000;          // 0 .. 765000 < E_EDGES
    if (ei32[2 * k + 1] != 0) atomicOr(&any_nonzero, 1);
    __syncthreads();
    if (threadIdx.x == 0) g_is64 = any_nonzero ? 0 : 1;
}

__global__ void zero_cnt_kernel() {
    int i = blockIdx.x * blockDim.x + threadIdx.x;
    if (i < N_NODES) g_cnt[i] = 0;
}

__device__ __forceinline__ void load_edge(const void* ei, int e, int& src, int& dst) {
    if (g_is64) {
        const long long* e64 = (const long long*)ei;
        src = (int)e64[e];
        dst = (int)e64[(size_t)E_EDGES + e];
    } else {
        const int* e32 = (const int*)ei;
        src = e32[e];
        dst = e32[(size_t)E_EDGES + e];
    }
}

// ---------------------------------------------------------------------------
// CSR build: histogram -> scan (also zeroes cursors) -> fill
// ---------------------------------------------------------------------------
__global__ void hist_kernel(const void* __restrict__ ei) {
    int e = blockIdx.x * blockDim.x + threadIdx.x;
    if (e >= E_EDGES) return;
    int src, dst;
    load_edge(ei, e, src, dst);
    if ((unsigned)src < N_NODES && (unsigned)dst < N_NODES)
        atomicAdd(&g_cnt[dst], 1);
}

#define SCAN_T 1024
#define CHUNK  49            // 1024*49 = 50176 >= 50001
__global__ void scan_kernel() {
    __shared__ int sh[SCAN_T];
    int t = threadIdx.x;
    int base = t * CHUNK;
    int sum = 0;
    #pragma unroll
    for (int i = 0; i < CHUNK; ++i) {
        int idx = base + i;
        if (idx < N_NODES) sum += g_cnt[idx];
    }
    sh[t] = sum;
    __syncthreads();
    for (int off = 1; off < SCAN_T; off <<= 1) {
        int v = (t >= off) ? sh[t - off] : 0;
        __syncthreads();
        sh[t] += v;
        __syncthreads();
    }
    int running = sh[t] - sum;   // exclusive base for this chunk
    #pragma unroll
    for (int i = 0; i < CHUNK; ++i) {
        int idx = base + i;
        if (idx <= N_NODES) g_row[idx] = running;
        if (idx < N_NODES) {
            running += g_cnt[idx];
            g_cur[idx] = 0;
        }
    }
}

__global__ void fill_kernel(const void* __restrict__ ei,
                            const float* __restrict__ ew) {
    int e = blockIdx.x * blockDim.x + threadIdx.x;
    if (e >= E_EDGES) return;
    int src, dst;
    load_edge(ei, e, src, dst);
    if ((unsigned)src >= N_NODES || (unsigned)dst >= N_NODES) return;
    int pos = g_row[dst] + atomicAdd(&g_cur[dst], 1);
    g_edge[pos] = make_int2(src, __float_as_int(ew[e]));
}

// ---------------------------------------------------------------------------
// Aggregate: one warp per dst node; lanes cover the 128-dim row (float4 each).
// 4-edge manual unroll -> 4 independent gathers in flight (MLP=4).
// ---------------------------------------------------------------------------
__device__ __forceinline__ float4 max4w(float4 a, float4 v, float w) {
    a.x = fmaxf(a.x, v.x * w);
    a.y = fmaxf(a.y, v.y * w);
    a.z = fmaxf(a.z, v.z * w);
    a.w = fmaxf(a.w, v.w * w);
    return a;
}

__global__ void agg_kernel(const float* __restrict__ x) {
    int warp = (blockIdx.x * blockDim.x + threadIdx.x) >> 5;
    if (warp >= N_NODES) return;
    int lane = threadIdx.x & 31;
    int beg = __ldg(&g_row[warp]);
    int end = __ldg(&g_row[warp + 1]);

    float4 acc = make_float4(NEG_INF_F, NEG_INF_F, NEG_INF_F, NEG_INF_F);
    int j = beg;
    for (; j + 4 <= end; j += 4) {
        int2 e0 = __ldg(&g_edge[j + 0]);
        int2 e1 = __ldg(&g_edge[j + 1]);
        int2 e2 = __ldg(&g_edge[j + 2]);
        int2 e3 = __ldg(&g_edge[j + 3]);
        float4 v0 = __ldg(&((const float4*)(x + (size_t)e0.x * DIM))[lane]);
        float4 v1 = __ldg(&((const float4*)(x + (size_t)e1.x * DIM))[lane]);
        float4 v2 = __ldg(&((const float4*)(x + (size_t)e2.x * DIM))[lane]);
        float4 v3 = __ldg(&((const float4*)(x + (size_t)e3.x * DIM))[lane]);
        acc = max4w(acc, v0, __int_as_float(e0.y));
        acc = max4w(acc, v1, __int_as_float(e1.y));
        acc = max4w(acc, v2, __int_as_float(e2.y));
        acc = max4w(acc, v3, __int_as_float(e3.y));
    }
    for (; j < end; ++j) {
        int2 ep = __ldg(&g_edge[j]);
        float4 v = __ldg(&((const float4*)(x + (size_t)ep.x * DIM))[lane]);
        acc = max4w(acc, v, __int_as_float(ep.y));
    }
    if (beg == end) acc = make_float4(0.f, 0.f, 0.f, 0.f);
    ((float4*)(g_agg + (size_t)warp * DIM))[lane] = acc;
}

// ---------------------------------------------------------------------------
// Packed fp32x2 helpers (sm_103a FFMA2 — PTX-only)
// ---------------------------------------------------------------------------
__device__ __forceinline__ unsigned long long pack2(float v) {
    unsigned long long r;
    asm("mov.b64 %0, {%1, %1};" : "=l"(r) : "f"(v));
    return r;
}
__device__ __forceinline__ void fma2(unsigned long long& d,
                                     unsigned long long a,
                                     unsigned long long b) {
    asm("fma.rn.f32x2 %0, %1, %2, %0;" : "+l"(d) : "l"(a), "l"(b));
}
__device__ __forceinline__ void unpack2(unsigned long long v, float& lo, float& hi) {
    asm("mov.b64 {%0, %1}, %2;" : "=f"(lo), "=f"(hi) : "l"(v));
}

// ---------------------------------------------------------------------------
// GEMM: OUT[m,o] = act( IN[m,:] @ W[o,:]^T + B[o] )
// FUSE_INPUT: IN = (1+eps)*x + agg.
// BM=64 x BN=128, 256 threads, thread tile 4 rows x 8 cols (4 f32x2 pairs).
// W transposed in smem (LDW=132, conflict-free LDS.128 reads).
// x tile k-major with XOR swizzle: word = k*64 + ((rg ^ (c4&15))<<2) + (r&3)
//   -> staging stores 2-way max, A-operand one aligned LDS.128 (broadcast).
// ---------------------------------------------------------------------------
#define LDW 132
#define BM  64
#define XS_WORDS (128 * 64)
#define SMEM_BYTES ((128 * LDW + XS_WORDS) * 4)   // 67584 + 32768 = 100352 B

__device__ __forceinline__ int xs_idx(int k, int r) {
    // swizzled word index for x-tile element (k, r); rg = r>>2, S = (k>>2)&15
    return k * 64 + ((((r >> 2) ^ (k >> 2)) & 15) << 2) + (r & 3);
}

template <bool FUSE_INPUT, bool LEAKY>
__global__ void __launch_bounds__(256, 2)
mlp_gemm_kernel(const float* __restrict__ A,
                const float* __restrict__ AGG,
                const float* __restrict__ W,
                const float* __restrict__ B,
                const float* __restrict__ EPS,
                float* __restrict__ OUT) {
    extern __shared__ float sm[];
    float* wT  = sm;                  // [k=128][o] stride LDW
    float* xsT = sm + 128 * LDW;      // swizzled k-major x tile

    const int tid = threadIdx.x;
    const int m0  = blockIdx.x * BM;
    const int tm  = tid >> 4;   // 0..15
    const int tn  = tid & 15;   // 0..15

    // Prefetch bias early (global latency hidden behind staging)
    float bias[8];
    #pragma unroll
    for (int j = 0; j < 8; ++j) bias[j] = __ldg(&B[tn * 8 + j]);

    // Stage W transposed: wT[k][o] = W[o*128 + k]
    for (int idx = tid; idx < 128 * 128; idx += 256) {
        int o = idx >> 7;
        int k = idx & 127;
        wT[k * LDW + o] = W[idx];
    }

    // Stage input tile k-major + swizzle (optionally fused with agg/eps)
    float scale = 1.0f;
    if (FUSE_INPUT) scale = 1.0f + EPS[0];
    #pragma unroll
    for (int p = 0; p < 8; ++p) {
        int r  = p * 8 + (tid >> 5);   // 0..63
        int c4 = tid & 31;             // float4 feature group (k = 4*c4+i)
        int m  = m0 + r;
        float4 v = make_float4(0.f, 0.f, 0.f, 0.f);
        if (m < N_NODES) {
            v = ((const float4*)(A + (size_t)m * DIM))[c4];
            if (FUSE_INPUT) {
                float4 g = ((const float4*)(AGG + (size_t)m * DIM))[c4];
                v.x = scale * v.x + g.x;
                v.y = scale * v.y + g.y;
                v.z = scale * v.z + g.z;
                v.w = scale * v.w + g.w;
            }
        }
        // note: for k = 4*c4 + i (i<4), (k>>2)&15 == c4&15 -> same swizzle
        int s = ((((r >> 2) ^ c4) & 15) << 2) + (r & 3);
        xsT[(c4 * 4 + 0) * 64 + s] = v.x;
        xsT[(c4 * 4 + 1) * 64 + s] = v.y;
        xsT[(c4 * 4 + 2) * 64 + s] = v.z;
        xsT[(c4 * 4 + 3) * 64 + s] = v.w;
    }
    __syncthreads();

    unsigned long long acc[4][4];
    #pragma unroll
    for (int i = 0; i < 4; ++i)
        #pragma unroll
        for (int j = 0; j < 4; ++j) acc[i][j] = 0ull;

    const float* bBase = wT + tn * 8;
    const int r0 = tm * 4;             // rows r0..r0+3, rg = tm

    #pragma unroll 8
    for (int k = 0; k < 128; ++k) {
        // A: 4 consecutive swizzled rows = one aligned LDS.128
        float4 av = *(const float4*)(xsT + k * 64 + (((tm ^ (k >> 2)) & 15) << 2));
        ulonglong2 bA = *(const ulonglong2*)(bBase + k * LDW);
        ulonglong2 bB = *(const ulonglong2*)(bBase + k * LDW + 4);
        unsigned long long a0 = pack2(av.x);
        unsigned long long a1 = pack2(av.y);
        unsigned long long a2 = pack2(av.z);
        unsigned long long a3 = pack2(av.w);
        fma2(acc[0][0], a0, bA.x); fma2(acc[0][1], a0, bA.y);
        fma2(acc[0][2], a0, bB.x); fma2(acc[0][3], a0, bB.y);
        fma2(acc[1][0], a1, bA.x); fma2(acc[1][1], a1, bA.y);
        fma2(acc[1][2], a1, bB.x); fma2(acc[1][3], a1, bB.y);
        fma2(acc[2][0], a2, bA.x); fma2(acc[2][1], a2, bA.y);
        fma2(acc[2][2], a2, bB.x); fma2(acc[2][3], a2, bB.y);
        fma2(acc[3][0], a3, bA.x); fma2(acc[3][1], a3, bA.y);
        fma2(acc[3][2], a3, bB.x); fma2(acc[3][3], a3, bB.y);
    }

    #pragma unroll
    for (int i = 0; i < 4; ++i) {
        int m = m0 + r0 + i;
        if (m < N_NODES) {
            float o[8];
            #pragma unroll
            for (int j = 0; j < 4; ++j) unpack2(acc[i][j], o[2 * j], o[2 * j + 1]);
            #pragma unroll
            for (int j = 0; j < 8; ++j) {
                float v = o[j] + bias[j];
                if (LEAKY) v = (v >= 0.0f) ? v : 0.01f * v;
                o[j] = v;
            }
            float4* dst = (float4*)(OUT + (size_t)m * DIM + tn * 8);
            dst[0] = make_float4(o[0], o[1], o[2], o[3]);
            dst[1] = make_float4(o[4], o[5], o[6], o[7]);
        }
    }
}

// ---------------------------------------------------------------------------
// Launcher — launch order fixed so ncu (-s 5) profiles agg_kernel.
// ---------------------------------------------------------------------------
extern "C" void kernel_launch(void* const* d_in, const int* in_sizes, int n_in,
                              void* d_out, int out_size) {
    const float* x   = (const float*)d_in[0];
    const void*  ei  = d_in[1];
    const float* ew  = (const float*)d_in[2];
    const float* w1  = (const float*)d_in[3];
    const float* b1  = (const float*)d_in[4];
    const float* w2  = (const float*)d_in[5];
    const float* b2  = (const float*)d_in[6];
    const float* eps = (const float*)d_in[7];
    float*       out = (float*)d_out;

    cudaFuncSetAttribute(mlp_gemm_kernel<true, true>,
                         cudaFuncAttributeMaxDynamicSharedMemorySize, SMEM_BYTES);
    cudaFuncSetAttribute(mlp_gemm_kernel<false, false>,
                         cudaFuncAttributeMaxDynamicSharedMemorySize, SMEM_BYTES);

    void *agg_p = nullptr, *h_p = nullptr;
    cudaGetSymbolAddress(&agg_p, g_agg);
    cudaGetSymbolAddress(&h_p,   g_h);
    float* agg = (float*)agg_p;
    float* h   = (float*)h_p;

    detect_dtype_kernel<<<1, 256>>>((const int*)ei);                 // 0
    zero_cnt_kernel<<<(N_NODES + 255) / 256, 256>>>();               // 1
    hist_kernel<<<(E_EDGES + 255) / 256, 256>>>(ei);                 // 2
    scan_kernel<<<1, SCAN_T>>>();                                    // 3
    fill_kernel<<<(E_EDGES + 255) / 256, 256>>>(ei, ew);             // 4
    agg_kernel<<<(N_NODES * 32 + 255) / 256, 256>>>(x);              // 5 <- ncu

    {
        int blocks = (N_NODES + BM - 1) / BM;
        mlp_gemm_kernel<true, true><<<blocks, 256, SMEM_BYTES>>>(    // 6
            x, agg, w1, b1, eps, h);
        mlp_gemm_kernel<false, false><<<blocks, 256, SMEM_BYTES>>>(  // 7
            h, nullptr, w2, b2, eps, out);
    }
}

// round 5
// speedup vs baseline: 2.2716x; 1.3388x over previous
#include <cuda_runtime.h>
#include <cstdint>

#define N_NODES 50000
#define E_EDGES 800000
#define DIM 128
#define NEG_INF_F __int_as_float(0xff800000)

#define SCAN_B 49          // 49 blocks * 1024 = 50176 >= N_NODES+1
#define SCAN_T 1024

// ---------------------------------------------------------------------------
// Static device scratch (no runtime allocation allowed)
// ---------------------------------------------------------------------------
__device__ float g_agg[(size_t)N_NODES * DIM];
__device__ float g_h[(size_t)N_NODES * DIM];
__device__ int   g_is64;                  // 1 if edge_index is int64, else int32
__device__ int   g_cnt[N_NODES];          // per-dst edge counts
__device__ int   g_row[N_NODES + 1];      // CSR row offsets
__device__ int   g_cur[N_NODES];          // fill cursors
__device__ int   g_blksum[SCAN_B];        // per-block scan sums
__device__ int2  g_edge[E_EDGES];         // {src, bits(weight)} bucketed by dst

// ---------------------------------------------------------------------------
// Kernel 0: zero g_cnt everywhere; block 0 also detects edge_index dtype
// (odd int32 words at spread positions are all-zero iff int64 layout).
// ---------------------------------------------------------------------------
__global__ void detzero_kernel(const int* __restrict__ ei32) {
    int i = blockIdx.x * blockDim.x + threadIdx.x;
    if (i < N_NODES) g_cnt[i] = 0;

    if (blockIdx.x == 0) {
        __shared__ int any_nonzero;
        if (threadIdx.x == 0) any_nonzero = 0;
        __syncthreads();
        int k = (int)threadIdx.x * 3000;          // 0 .. 765000 < E_EDGES
        if (ei32[2 * k + 1] != 0) atomicOr(&any_nonzero, 1);
        __syncthreads();
        if (threadIdx.x == 0) g_is64 = any_nonzero ? 0 : 1;
    }
}

__device__ __forceinline__ void load_edge(const void* ei, int e, int& src, int& dst) {
    if (g_is64) {
        const long long* e64 = (const long long*)ei;
        src = (int)e64[e];
        dst = (int)e64[(size_t)E_EDGES + e];
    } else {
        const int* e32 = (const int*)ei;
        src = e32[e];
        dst = e32[(size_t)E_EDGES + e];
    }
}

// ---------------------------------------------------------------------------
// CSR build: histogram -> (scanA, scanApply) -> fill
// ---------------------------------------------------------------------------
__global__ void hist_kernel(const void* __restrict__ ei) {
    int e = blockIdx.x * blockDim.x + threadIdx.x;
    if (e >= E_EDGES) return;
    int src, dst;
    load_edge(ei, e, src, dst);
    if ((unsigned)src < N_NODES && (unsigned)dst < N_NODES)
        atomicAdd(&g_cnt[dst], 1);
}

// scanA: each block (1024 threads) scans its 1024 counts; writes local
// EXCLUSIVE prefix into g_row[idx] (idx <= N_NODES) and block total.
__global__ void scanA_kernel() {
    __shared__ int sh[SCAN_T];
    int t = threadIdx.x;
    int idx = blockIdx.x * SCAN_T + t;
    int c = (idx < N_NODES) ? g_cnt[idx] : 0;
    sh[t] = c;
    __syncthreads();
    #pragma unroll
    for (int off = 1; off < SCAN_T; off <<= 1) {
        int v = (t >= off) ? sh[t - off] : 0;
        __syncthreads();
        sh[t] += v;
        __syncthreads();
    }
    if (idx <= N_NODES) g_row[idx] = sh[t] - c;   // exclusive
    if (t == SCAN_T - 1) g_blksum[blockIdx.x] = sh[t];
}

// scanApply: each block redundantly scans the 49 block sums in smem, then
// adds its block offset to g_row and zeroes g_cur.
__global__ void scanApply_kernel() {
    __shared__ int sums[64];
    int t = threadIdx.x;
    if (t < 64) sums[t] = (t < SCAN_B) ? g_blksum[t] : 0;
    __syncthreads();
    if (t < 64) {
        // inclusive scan over 64 entries (single warp-pair, smem H-S)
        #pragma unroll
        for (int off = 1; off < 64; off <<= 1) {
            int v = (t >= off) ? sums[t - off] : 0;
            __syncthreads();
            sums[t] += v;
            __syncthreads();
        }
    } else {
        #pragma unroll
        for (int off = 1; off < 64; off <<= 1) { __syncthreads(); __syncthreads(); }
    }
    __syncthreads();
    int offset = (blockIdx.x == 0) ? 0 : sums[blockIdx.x - 1];
    int idx = blockIdx.x * SCAN_T + t;
    if (idx <= N_NODES) g_row[idx] += offset;
    if (idx < N_NODES) g_cur[idx] = 0;
}

__global__ void fill_kernel(const void* __restrict__ ei,
                            const float* __restrict__ ew) {
    int e = blockIdx.x * blockDim.x + threadIdx.x;
    if (e >= E_EDGES) return;
    int src, dst;
    load_edge(ei, e, src, dst);
    if ((unsigned)src >= N_NODES || (unsigned)dst >= N_NODES) return;
    int pos = g_row[dst] + atomicAdd(&g_cur[dst], 1);
    g_edge[pos] = make_int2(src, __float_as_int(ew[e]));
}

// ---------------------------------------------------------------------------
// Aggregate: one warp per dst node; lanes cover the 128-dim row (float4 each).
// 4-edge manual unroll -> 4 independent gathers in flight.
// ---------------------------------------------------------------------------
__device__ __forceinline__ float4 max4w(float4 a, float4 v, float w) {
    a.x = fmaxf(a.x, v.x * w);
    a.y = fmaxf(a.y, v.y * w);
    a.z = fmaxf(a.z, v.z * w);
    a.w = fmaxf(a.w, v.w * w);
    return a;
}

__global__ void agg_kernel(const float* __restrict__ x) {
    int warp = (blockIdx.x * blockDim.x + threadIdx.x) >> 5;
    if (warp >= N_NODES) return;
    int lane = threadIdx.x & 31;
    int beg = __ldg(&g_row[warp]);
    int end = __ldg(&g_row[warp + 1]);

    float4 acc = make_float4(NEG_INF_F, NEG_INF_F, NEG_INF_F, NEG_INF_F);
    int j = beg;
    for (; j + 4 <= end; j += 4) {
        int2 e0 = __ldg(&g_edge[j + 0]);
        int2 e1 = __ldg(&g_edge[j + 1]);
        int2 e2 = __ldg(&g_edge[j + 2]);
        int2 e3 = __ldg(&g_edge[j + 3]);
        float4 v0 = __ldg(&((const float4*)(x + (size_t)e0.x * DIM))[lane]);
        float4 v1 = __ldg(&((const float4*)(x + (size_t)e1.x * DIM))[lane]);
        float4 v2 = __ldg(&((const float4*)(x + (size_t)e2.x * DIM))[lane]);
        float4 v3 = __ldg(&((const float4*)(x + (size_t)e3.x * DIM))[lane]);
        acc = max4w(acc, v0, __int_as_float(e0.y));
        acc = max4w(acc, v1, __int_as_float(e1.y));
        acc = max4w(acc, v2, __int_as_float(e2.y));
        acc = max4w(acc, v3, __int_as_float(e3.y));
    }
    for (; j < end; ++j) {
        int2 ep = __ldg(&g_edge[j]);
        float4 v = __ldg(&((const float4*)(x + (size_t)ep.x * DIM))[lane]);
        acc = max4w(acc, v, __int_as_float(ep.y));
    }
    if (beg == end) acc = make_float4(0.f, 0.f, 0.f, 0.f);
    ((float4*)(g_agg + (size_t)warp * DIM))[lane] = acc;
}

// ---------------------------------------------------------------------------
// Packed fp32x2 helpers (sm_103a FFMA2 — PTX-only)
// ---------------------------------------------------------------------------
__device__ __forceinline__ unsigned long long pack2(float v) {
    unsigned long long r;
    asm("mov.b64 %0, {%1, %1};" : "=l"(r) : "f"(v));
    return r;
}
__device__ __forceinline__ void fma2(unsigned long long& d,
                                     unsigned long long a,
                                     unsigned long long b) {
    asm("fma.rn.f32x2 %0, %1, %2, %0;" : "+l"(d) : "l"(a), "l"(b));
}
__device__ __forceinline__ void unpack2(unsigned long long v, float& lo, float& hi) {
    asm("mov.b64 {%0, %1}, %2;" : "=f"(lo), "=f"(hi) : "l"(v));
}

// ---------------------------------------------------------------------------
// GEMM: OUT[m,o] = act( IN[m,:] @ W[o,:]^T + B[o] )   (unchanged from R4)
// ---------------------------------------------------------------------------
#define LDW 132
#define BM  64
#define XS_WORDS (128 * 64)
#define SMEM_BYTES ((128 * LDW + XS_WORDS) * 4)   // 100352 B

template <bool FUSE_INPUT, bool LEAKY>
__global__ void __launch_bounds__(256, 2)
mlp_gemm_kernel(const float* __restrict__ A,
                const float* __restrict__ AGG,
                const float* __restrict__ W,
                const float* __restrict__ B,
                const float* __restrict__ EPS,
                float* __restrict__ OUT) {
    extern __shared__ float sm[];
    float* wT  = sm;                  // [k=128][o] stride LDW
    float* xsT = sm + 128 * LDW;      // swizzled k-major x tile

    const int tid = threadIdx.x;
    const int m0  = blockIdx.x * BM;
    const int tm  = tid >> 4;   // 0..15
    const int tn  = tid & 15;   // 0..15

    float bias[8];
    #pragma unroll
    for (int j = 0; j < 8; ++j) bias[j] = __ldg(&B[tn * 8 + j]);

    for (int idx = tid; idx < 128 * 128; idx += 256) {
        int o = idx >> 7;
        int k = idx & 127;
        wT[k * LDW + o] = W[idx];
    }

    float scale = 1.0f;
    if (FUSE_INPUT) scale = 1.0f + EPS[0];
    #pragma unroll
    for (int p = 0; p < 8; ++p) {
        int r  = p * 8 + (tid >> 5);   // 0..63
        int c4 = tid & 31;             // float4 feature group (k = 4*c4+i)
        int m  = m0 + r;
        float4 v = make_float4(0.f, 0.f, 0.f, 0.f);
        if (m < N_NODES) {
            v = ((const float4*)(A + (size_t)m * DIM))[c4];
            if (FUSE_INPUT) {
                float4 g = ((const float4*)(AGG + (size_t)m * DIM))[c4];
                v.x = scale * v.x + g.x;
                v.y = scale * v.y + g.y;
                v.z = scale * v.z + g.z;
                v.w = scale * v.w + g.w;
            }
        }
        int s = ((((r >> 2) ^ c4) & 15) << 2) + (r & 3);
        xsT[(c4 * 4 + 0) * 64 + s] = v.x;
        xsT[(c4 * 4 + 1) * 64 + s] = v.y;
        xsT[(c4 * 4 + 2) * 64 + s] = v.z;
        xsT[(c4 * 4 + 3) * 64 + s] = v.w;
    }
    __syncthreads();

    unsigned long long acc[4][4];
    #pragma unroll
    for (int i = 0; i < 4; ++i)
        #pragma unroll
        for (int j = 0; j < 4; ++j) acc[i][j] = 0ull;

    const float* bBase = wT + tn * 8;
    const int r0 = tm * 4;

    #pragma unroll 8
    for (int k = 0; k < 128; ++k) {
        float4 av = *(const float4*)(xsT + k * 64 + (((tm ^ (k >> 2)) & 15) << 2));
        ulonglong2 bA = *(const ulonglong2*)(bBase + k * LDW);
        ulonglong2 bB = *(const ulonglong2*)(bBase + k * LDW + 4);
        unsigned long long a0 = pack2(av.x);
        unsigned long long a1 = pack2(av.y);
        unsigned long long a2 = pack2(av.z);
        unsigned long long a3 = pack2(av.w);
        fma2(acc[0][0], a0, bA.x); fma2(acc[0][1], a0, bA.y);
        fma2(acc[0][2], a0, bB.x); fma2(acc[0][3], a0, bB.y);
        fma2(acc[1][0], a1, bA.x); fma2(acc[1][1], a1, bA.y);
        fma2(acc[1][2], a1, bB.x); fma2(acc[1][3], a1, bB.y);
        fma2(acc[2][0], a2, bA.x); fma2(acc[2][1], a2, bA.y);
        fma2(acc[2][2], a2, bB.x); fma2(acc[2][3], a2, bB.y);
        fma2(acc[3][0], a3, bA.x); fma2(acc[3][1], a3, bA.y);
        fma2(acc[3][2], a3, bB.x); fma2(acc[3][3], a3, bB.y);
    }

    #pragma unroll
    for (int i = 0; i < 4; ++i) {
        int m = m0 + r0 + i;
        if (m < N_NODES) {
            float o[8];
            #pragma unroll
            for (int j = 0; j < 4; ++j) unpack2(acc[i][j], o[2 * j], o[2 * j + 1]);
            #pragma unroll
            for (int j = 0; j < 8; ++j) {
                float v = o[j] + bias[j];
                if (LEAKY) v = (v >= 0.0f) ? v : 0.01f * v;
                o[j] = v;
            }
            float4* dst = (float4*)(OUT + (size_t)m * DIM + tn * 8);
            dst[0] = make_float4(o[0], o[1], o[2], o[3]);
            dst[1] = make_float4(o[4], o[5], o[6], o[7]);
        }
    }
}

// ---------------------------------------------------------------------------
// Launcher — launch #5 (0-based) is agg_kernel for ncu -s 5 -c 1.
// ---------------------------------------------------------------------------
extern "C" void kernel_launch(void* const* d_in, const int* in_sizes, int n_in,
                              void* d_out, int out_size) {
    const float* x   = (const float*)d_in[0];
    const void*  ei  = d_in[1];
    const float* ew  = (const float*)d_in[2];
    const float* w1  = (const float*)d_in[3];
    const float* b1  = (const float*)d_in[4];
    const float* w2  = (const float*)d_in[5];
    const float* b2  = (const float*)d_in[6];
    const float* eps = (const float*)d_in[7];
    float*       out = (float*)d_out;

    cudaFuncSetAttribute(mlp_gemm_kernel<true, true>,
                         cudaFuncAttributeMaxDynamicSharedMemorySize, SMEM_BYTES);
    cudaFuncSetAttribute(mlp_gemm_kernel<false, false>,
                         cudaFuncAttributeMaxDynamicSharedMemorySize, SMEM_BYTES);

    void *agg_p = nullptr, *h_p = nullptr;
    cudaGetSymbolAddress(&agg_p, g_agg);
    cudaGetSymbolAddress(&h_p,   g_h);
    float* agg = (float*)agg_p;
    float* h   = (float*)h_p;

    detzero_kernel<<<(N_NODES + 255) / 256, 256>>>((const int*)ei);  // 0
    hist_kernel<<<(E_EDGES + 255) / 256, 256>>>(ei);                 // 1
    scanA_kernel<<<SCAN_B, SCAN_T>>>();                              // 2
    scanApply_kernel<<<SCAN_B, SCAN_T>>>();                          // 3
    fill_kernel<<<(E_EDGES + 255) / 256, 256>>>(ei, ew);             // 4
    agg_kernel<<<(N_NODES * 32 + 255) / 256, 256>>>(x);              // 5 <- ncu

    {
        int blocks = (N_NODES + BM - 1) / BM;
        mlp_gemm_kernel<true, true><<<blocks, 256, SMEM_BYTES>>>(    // 6
            x, agg, w1, b1, eps, h);
        mlp_gemm_kernel<false, false><<<blocks, 256, SMEM_BYTES>>>(  // 7
            h, nullptr, w2, b2, eps, out);
    }
}